// round 11
// baseline (speedup 1.0000x reference)
#include <cuda_runtime.h>
#include <cstdint>

#define KTOP 2048
#define DD 128
#define HBINS 8192            // 13-bit key prefix (fallback path)
#define HSHIFT 19
#define CAND_MAX 6144
#define TS_VAL 2.42f          // speculative threshold; exact path verifies bounds
#define TPB 512
#define NB_CAP 1024

// ---- static scratch (no allocations allowed) ----
__device__ unsigned int g_hist[HBINS];          // fallback only (kept zeroed)
__device__ float g_y[500224];
__device__ unsigned int g_cnt;
__device__ unsigned int g_cnt2;
__device__ unsigned int g_done;
__device__ unsigned int g_tick;
__device__ __align__(16) unsigned long long g_cand[CAND_MAX];
__device__ unsigned int g_bar_count;
__device__ volatile unsigned int g_bar_gen;

// monotonic unsigned key for f32 ordering
__device__ __forceinline__ unsigned int fkey(float f) {
    unsigned int u = __float_as_uint(f);
    return (u & 0x80000000u) ? ~u : (u | 0x80000000u);
}
__device__ __forceinline__ float dot4(float4 a, float4 b) {
    return a.x * b.x + a.y * b.y + a.z * b.z + a.w * b.w;
}

// software grid barrier (all blocks co-resident by construction)
__device__ __forceinline__ void grid_bar(int nb) {
    __threadfence();
    __syncthreads();
    if (threadIdx.x == 0) {
        unsigned int gen = g_bar_gen;
        if (atomicAdd(&g_bar_count, 1u) == (unsigned int)(nb - 1)) {
            g_bar_count = 0u;
            __threadfence();
            g_bar_gen = gen + 1u;
        } else {
            while (g_bar_gen == gen) { __nanosleep(64); }
        }
    }
    __syncthreads();
}

__device__ __forceinline__ void push_cand(float y, int i, unsigned int* cnt) {
    unsigned int key = fkey(y);
    unsigned int pos = atomicAdd(cnt, 1u);
    if (pos < CAND_MAX) {
        // value-descending major, index-ascending minor
        g_cand[pos] = ((unsigned long long)key << 32) |
                      (unsigned long long)(~(unsigned int)i);
    }
}

// 8-row dot body: rows (r0+grp) and (r0+grp+4), 8 lanes per row
#define DOT8(r0) do {                                                         \
    int _rA = (r0) + grp;                                                     \
    const float4* _xa = x4 + (size_t)_rA * 32 + l8;                           \
    const float4* _xb = _xa + 4 * 32;                                         \
    float4 _a0 = __ldcs(_xa + 0),  _a1 = __ldcs(_xa + 8),                     \
           _a2 = __ldcs(_xa + 16), _a3 = __ldcs(_xa + 24);                    \
    float4 _b0 = __ldcs(_xb + 0),  _b1 = __ldcs(_xb + 8),                     \
           _b2 = __ldcs(_xb + 16), _b3 = __ldcs(_xb + 24);                    \
    float _sA = (dot4(_a0, q0) + dot4(_a1, q1)) + (dot4(_a2, q2) + dot4(_a3, q3)); \
    float _sB = (dot4(_b0, q0) + dot4(_b1, q1)) + (dot4(_b2, q2) + dot4(_b3, q3)); \
    _sA += __shfl_xor_sync(0xffffffffu, _sA, 1);                              \
    _sB += __shfl_xor_sync(0xffffffffu, _sB, 1);                              \
    _sA += __shfl_xor_sync(0xffffffffu, _sA, 2);                              \
    _sB += __shfl_xor_sync(0xffffffffu, _sB, 2);                              \
    _sA += __shfl_xor_sync(0xffffffffu, _sA, 4);                              \
    _sB += __shfl_xor_sync(0xffffffffu, _sB, 4);                              \
    if (l8 == 0) {                                                            \
        float _yA = _sA * inv;                                                \
        float _yB = _sB * inv;                                                \
        g_y[_rA] = _yA;                                                       \
        g_y[_rA + 4] = _yB;                                                   \
        if (_yA >= TS_VAL) push_cand(_yA, _rA, &g_cnt);                       \
        if (_yB >= TS_VAL) push_cand(_yB, _rA + 4, &g_cnt);                   \
    }                                                                         \
} while (0)

__global__ void __launch_bounds__(TPB, 2)
mega(const float* __restrict__ x, const float* __restrict__ p,
     float* __restrict__ out, int n, int nb)
{
    const int tid = threadIdx.x;
    const int lane = tid & 31;
    const int l8 = lane & 7;
    const int grp = lane >> 3;
    const int wib = tid >> 5;
    const int gtid = blockIdx.x * TPB + tid;
    const int gthreads = nb * TPB;
    const int wid = gtid >> 5;
    const int nw = gthreads >> 5;

    // union: rank keys (6144 u64 = 48 KB) / fallback smem hist (8192 u32 = 32 KB)
    __shared__ __align__(16) unsigned char sbuf[CAND_MAX * 8];
    unsigned long long* sk = reinterpret_cast<unsigned long long*>(sbuf);
    unsigned int* shist = reinterpret_cast<unsigned int*>(sbuf);
    __shared__ unsigned int ss[TPB];
    __shared__ unsigned int swt[16], saf[16];
    __shared__ unsigned int s_tbin;
    __shared__ int s_rk[64];
    __shared__ int s_ridx[64];
    __shared__ float s_rt[64];

    // ---- phase 0: norm (per-warp, registers only) ----
    const float4* __restrict__ p4 = reinterpret_cast<const float4*>(p);
    float4 q0 = p4[l8], q1 = p4[l8 + 8], q2 = p4[l8 + 16], q3 = p4[l8 + 24];
    float s2 = (dot4(q0, q0) + dot4(q1, q1)) + (dot4(q2, q2) + dot4(q3, q3));
    s2 += __shfl_xor_sync(0xffffffffu, s2, 1);
    s2 += __shfl_xor_sync(0xffffffffu, s2, 2);
    s2 += __shfl_xor_sync(0xffffffffu, s2, 4);
    const float inv = 1.0f / sqrtf(s2);

    // ---- phase 1: coalesced dot + speculative push ----
    // static 7/8 interleaved, then 8-row work-stealing tickets (skew absorber)
    const float4* __restrict__ x4 = reinterpret_cast<const float4*>(x);
    const int n8 = n & ~7;
    const int nstat = (int)(((long long)n8 * 7 / 8)) & ~7;

    for (int r0 = wid * 8; r0 < nstat; r0 += nw * 8) {
        DOT8(r0);
    }
    // dynamic tail region [nstat, n8) in 8-row tickets, next-ticket prefetched
    {
        unsigned int t;
        if (lane == 0) t = atomicAdd(&g_tick, 1u);
        t = __shfl_sync(0xffffffffu, t, 0);
        for (;;) {
            int base = nstat + (int)t * 8;
            if (base >= n8) break;
            unsigned int tn;
            if (lane == 0) tn = atomicAdd(&g_tick, 1u);
            tn = __shfl_sync(0xffffffffu, tn, 0);
            DOT8(base);
            t = tn;
        }
    }
    // tail rows [n8, n): block 0 / warp 0
    if (blockIdx.x == 0 && tid < 32 && n8 < n) {
        float4 pl = p4[lane];
        for (int r = n8; r < n; r++) {
            float4 v = x4[(size_t)r * 32 + lane];
            float s = dot4(v, pl);
            #pragma unroll
            for (int o = 16; o; o >>= 1) s += __shfl_xor_sync(0xffffffffu, s, o);
            if (lane == 0) {
                float y = s * inv;
                g_y[r] = y;
                if (y >= TS_VAL) push_cand(y, r, &g_cnt);
            }
        }
    }
    grid_bar(nb);

    unsigned int c1 = g_cnt;
    // handshake: reset counters once every block has read them
    if (tid == 0) {
        if (atomicAdd(&g_done, 1u) + 1u == (unsigned int)nb) {
            g_cnt = 0u;
            g_tick = 0u;
            g_done = 0u;
        }
    }

    int C;
    if (c1 >= KTOP && c1 <= CAND_MAX) {
        C = (int)c1;                       // fast path: candidates complete
    } else {
        // ===== fallback (exact, rare): histogram -> threshold -> compact =====
        for (int i = tid; i < HBINS; i += TPB) shist[i] = 0u;
        __syncthreads();
        for (int r = gtid; r < n; r += gthreads)
            atomicAdd(&shist[fkey(g_y[r]) >> HSHIFT], 1u);
        __syncthreads();
        for (int i = tid; i < HBINS; i += TPB) {
            unsigned int v = shist[i];
            if (v) atomicAdd(&g_hist[i], v);
        }
        grid_bar(nb);
        // threshold bin (every block, redundant)
        {
            const uint4* h4 = reinterpret_cast<const uint4*>(g_hist) + tid * 4;
            uint4 a = h4[0], b = h4[1], c = h4[2], d = h4[3];
            unsigned int part = a.x + a.y + a.z + a.w + b.x + b.y + b.z + b.w
                              + c.x + c.y + c.z + c.w + d.x + d.y + d.z + d.w;
            unsigned int s = part;
            #pragma unroll
            for (int off = 1; off < 32; off <<= 1) {
                unsigned int v = __shfl_down_sync(0xffffffffu, s, off);
                if (lane + off < 32) s += v;
            }
            if (lane == 0) swt[wib] = s;
            __syncthreads();
            if (tid < 16) {
                unsigned int acc = 0;
                for (int i = tid + 1; i < 16; i++) acc += swt[i];
                saf[tid] = acc;
            }
            __syncthreads();
            unsigned int incl = s + saf[wib];
            unsigned int nxt = incl - part;
            if (incl >= KTOP && nxt < KTOP) {
                unsigned int acc = nxt;
                for (int bi = tid * 16 + 15; bi >= tid * 16; bi--) {
                    acc += g_hist[bi];
                    if (acc >= KTOP) { s_tbin = (unsigned int)bi; break; }
                }
            }
            __syncthreads();
        }
        // compact using exact bin threshold
        {
            unsigned int tb = s_tbin;
            for (int r = gtid; r < n; r += gthreads) {
                float y = g_y[r];
                if ((fkey(y) >> HSHIFT) >= tb) push_cand(y, r, &g_cnt2);
            }
        }
        grid_bar(nb);
        unsigned int c2 = g_cnt2;
        if (tid == 0) {
            if (atomicAdd(&g_done, 1u) + 1u == (unsigned int)nb) {
                g_cnt2 = 0u;
                g_done = 0u;
            }
        }
        for (int i = tid; i < HBINS; i += TPB) shist[i] = 0u;   // clear union before sk use
        for (int i = gtid; i < HBINS; i += gthreads) g_hist[i] = 0u;
        C = (int)min(c2, (unsigned int)CAND_MAX);
        grid_bar(nb);      // hist reads done & cand writes visible before rank
    }

    // ---- rank + gather + write (fused): 64 candidates/block ----
    {
        int nactive = (C + 63) >> 6;
        if (blockIdx.x < nactive) {
            for (int i = tid; i < C; i += TPB) sk[i] = g_cand[i];
            __syncthreads();
            int j = tid & 63;
            int seg = tid >> 6;            // 8 segments
            int jg = blockIdx.x * 64 + j;
            unsigned long long pk = (jg < C) ? sk[jg] : ~0ull;
            int segsz = (C + 7) >> 3;
            int lo = seg * segsz;
            int hi = lo + segsz; if (hi > C) hi = C;
            int part = 0;
            int i = lo;
            for (; i + 4 <= hi; i += 4) {
                part += (sk[i + 0] > pk);
                part += (sk[i + 1] > pk);
                part += (sk[i + 2] > pk);
                part += (sk[i + 3] > pk);
            }
            for (; i < hi; i++) part += (sk[i] > pk);
            ss[tid] = (unsigned int)part;
            __syncthreads();
            if (tid < 64) {
                int rk = -1, idx = 0;
                float tv = 0.f;
                if (jg < C) {
                    int rank = (int)(ss[tid] + ss[tid + 64] + ss[tid + 128] +
                                     ss[tid + 192] + ss[tid + 256] + ss[tid + 320] +
                                     ss[tid + 384] + ss[tid + 448]);
                    if (rank < KTOP) {
                        unsigned int key = (unsigned int)(pk >> 32);
                        unsigned int u = (key & 0x80000000u) ? (key ^ 0x80000000u) : ~key;
                        rk = rank;
                        idx = (int)(~(unsigned int)(pk & 0xFFFFFFFFull));
                        tv = tanhf(__uint_as_float(u));
                    }
                }
                s_rk[tid] = rk;
                s_ridx[tid] = idx;
                s_rt[tid] = tv;
            }
            __syncthreads();
            // gather + write: 8 threads per candidate
            {
                int c = tid >> 3;
                int sg = tid & 7;
                int rk = s_rk[c];
                if (rk >= 0) {
                    int idx = s_ridx[c];
                    float tv = s_rt[c];
                    const float4* xr = x4 + (size_t)idx * 32 + sg;
                    float4* orow = reinterpret_cast<float4*>(out) + (size_t)rk * 32 + sg;
                    float4 v0 = xr[0], v1 = xr[8], v2 = xr[16], v3 = xr[24];
                    orow[0]  = make_float4(v0.x * tv, v0.y * tv, v0.z * tv, v0.w * tv);
                    orow[8]  = make_float4(v1.x * tv, v1.y * tv, v1.z * tv, v1.w * tv);
                    orow[16] = make_float4(v2.x * tv, v2.y * tv, v2.z * tv, v2.w * tv);
                    orow[24] = make_float4(v3.x * tv, v3.y * tv, v3.z * tv, v3.w * tv);
                }
            }
        }
    }
}

extern "C" void kernel_launch(void* const* d_in, const int* in_sizes, int n_in,
                              void* d_out, int out_size) {
    const float* x = (const float*)d_in[0];
    const float* p = (const float*)d_in[1];
    int n = in_sizes[0] / DD;

    int dev = 0;
    cudaGetDevice(&dev);
    int sm = 0;
    cudaDeviceGetAttribute(&sm, cudaDevAttrMultiProcessorCount, dev);
    int bpsm = 0;
    cudaOccupancyMaxActiveBlocksPerMultiprocessor(&bpsm, mega, TPB, 0);
    if (bpsm < 1) bpsm = 1;
    int nb = sm * bpsm;
    if (nb > NB_CAP) nb = NB_CAP;

    mega<<<nb, TPB>>>(x, p, (float*)d_out, n, nb);
}

// round 12
// speedup vs baseline: 1.0103x; 1.0103x over previous
#include <cuda_runtime.h>
#include <cstdint>

#define KTOP 2048
#define DD 128
#define HBINS 8192            // 13-bit key prefix (fallback path)
#define HSHIFT 19
#define CAND_MAX 6144
#define TS_VAL 2.42f          // speculative threshold; exact path verifies bounds
#define TPB 512
#define NB_CAP 1024

// ---- static scratch (no allocations allowed) ----
__device__ unsigned int g_hist[HBINS];          // fallback only (kept zeroed)
__device__ float g_y[500224];
__device__ unsigned int g_cnt;
__device__ unsigned int g_cnt2;
__device__ unsigned int g_done;
__device__ __align__(16) unsigned long long g_cand[CAND_MAX];
__device__ unsigned int g_bar_count;
__device__ volatile unsigned int g_bar_gen;

// monotonic unsigned key for f32 ordering
__device__ __forceinline__ unsigned int fkey(float f) {
    unsigned int u = __float_as_uint(f);
    return (u & 0x80000000u) ? ~u : (u | 0x80000000u);
}
__device__ __forceinline__ float dot4(float4 a, float4 b) {
    return a.x * b.x + a.y * b.y + a.z * b.z + a.w * b.w;
}

// software grid barrier (all blocks co-resident by construction)
__device__ __forceinline__ void grid_bar(int nb) {
    __threadfence();
    __syncthreads();
    if (threadIdx.x == 0) {
        unsigned int gen = g_bar_gen;
        if (atomicAdd(&g_bar_count, 1u) == (unsigned int)(nb - 1)) {
            g_bar_count = 0u;
            __threadfence();
            g_bar_gen = gen + 1u;
        } else {
            while (g_bar_gen == gen) { __nanosleep(64); }
        }
    }
    __syncthreads();
}

__device__ __forceinline__ void push_cand(float y, int i, unsigned int* cnt) {
    unsigned int key = fkey(y);
    unsigned int pos = atomicAdd(cnt, 1u);
    if (pos < CAND_MAX) {
        // value-descending major, index-ascending minor
        g_cand[pos] = ((unsigned long long)key << 32) |
                      (unsigned long long)(~(unsigned int)i);
    }
}

// 4-row group: each 8-lane subgroup handles one row; 4 float4 loads per lane
#define LOAD4(c0,c1,c2,c3, r0) do {                                          \
    const float4* _xp = x4 + (size_t)((r0) + grp) * 32 + l8;                 \
    c0 = __ldcs(_xp + 0);  c1 = __ldcs(_xp + 8);                             \
    c2 = __ldcs(_xp + 16); c3 = __ldcs(_xp + 24);                            \
} while (0)

#define COMP4(c0,c1,c2,c3, r0) do {                                          \
    float _s = (dot4(c0, q0) + dot4(c1, q1)) + (dot4(c2, q2) + dot4(c3, q3));\
    _s += __shfl_xor_sync(0xffffffffu, _s, 1);                               \
    _s += __shfl_xor_sync(0xffffffffu, _s, 2);                               \
    _s += __shfl_xor_sync(0xffffffffu, _s, 4);                               \
    if (l8 == 0) {                                                           \
        int _r = (r0) + grp;                                                 \
        float _y = _s * inv;                                                 \
        g_y[_r] = _y;                                                        \
        if (_y >= TS_VAL) push_cand(_y, _r, &g_cnt);                         \
    }                                                                        \
} while (0)

__global__ void __launch_bounds__(TPB, 2)
mega(const float* __restrict__ x, const float* __restrict__ p,
     float* __restrict__ out, int n, int nb)
{
    const int tid = threadIdx.x;
    const int lane = tid & 31;
    const int l8 = lane & 7;
    const int grp = lane >> 3;
    const int wib = tid >> 5;
    const int gtid = blockIdx.x * TPB + tid;
    const int gthreads = nb * TPB;
    const int wid = gtid >> 5;
    const int nw = gthreads >> 5;

    // union: rank keys (6144 u64 = 48 KB) / fallback smem hist (8192 u32 = 32 KB)
    __shared__ __align__(16) unsigned char sbuf[CAND_MAX * 8];
    unsigned long long* sk = reinterpret_cast<unsigned long long*>(sbuf);
    unsigned int* shist = reinterpret_cast<unsigned int*>(sbuf);
    __shared__ unsigned int ss[TPB];
    __shared__ unsigned int swt[16], saf[16];
    __shared__ unsigned int s_tbin;
    __shared__ int s_rk[64];
    __shared__ int s_ridx[64];
    __shared__ float s_rt[64];

    // ---- phase 0: norm (per-warp, registers only) ----
    const float4* __restrict__ p4 = reinterpret_cast<const float4*>(p);
    float4 q0 = p4[l8], q1 = p4[l8 + 8], q2 = p4[l8 + 16], q3 = p4[l8 + 24];
    float s2 = (dot4(q0, q0) + dot4(q1, q1)) + (dot4(q2, q2) + dot4(q3, q3));
    s2 += __shfl_xor_sync(0xffffffffu, s2, 1);
    s2 += __shfl_xor_sync(0xffffffffu, s2, 2);
    s2 += __shfl_xor_sync(0xffffffffu, s2, 4);
    const float inv = 1.0f / sqrtf(s2);

    // ---- phase 1: ping-pong pipelined coalesced dot + speculative push ----
    const float4* __restrict__ x4 = reinterpret_cast<const float4*>(x);
    const int n4a = n & ~3;
    const int stride4 = nw * 4;
    {
        const int wbase = wid * 4;
        int niter = (wbase < n4a) ? ((n4a - 1 - wbase) / stride4 + 1) : 0;
        float4 a0, a1, a2, a3;
        float4 b0, b1, b2, b3;
        if (niter > 0) LOAD4(a0, a1, a2, a3, wbase);
        int i = 0;
        for (; i + 2 <= niter; i += 2) {
            int rcur = wbase + i * stride4;
            int rmid = rcur + stride4;
            LOAD4(b0, b1, b2, b3, rmid);
            COMP4(a0, a1, a2, a3, rcur);
            if (i + 2 < niter) {
                int rnxt = rmid + stride4;
                LOAD4(a0, a1, a2, a3, rnxt);
            }
            COMP4(b0, b1, b2, b3, rmid);
        }
        if (i < niter) {
            COMP4(a0, a1, a2, a3, wbase + i * stride4);
        }
    }
    // tail rows [n4a, n): block 0 / warp 0, full-width dot
    if (blockIdx.x == 0 && tid < 32 && n4a < n) {
        float4 pl = p4[lane];
        for (int r = n4a; r < n; r++) {
            float4 v = x4[(size_t)r * 32 + lane];
            float s = dot4(v, pl);
            #pragma unroll
            for (int o = 16; o; o >>= 1) s += __shfl_xor_sync(0xffffffffu, s, o);
            if (lane == 0) {
                float y = s * inv;
                g_y[r] = y;
                if (y >= TS_VAL) push_cand(y, r, &g_cnt);
            }
        }
    }
    grid_bar(nb);

    unsigned int c1 = g_cnt;
    // handshake: reset g_cnt once every block has read it
    if (tid == 0) {
        if (atomicAdd(&g_done, 1u) + 1u == (unsigned int)nb) {
            g_cnt = 0u;
            g_done = 0u;
        }
    }

    int C;
    if (c1 >= KTOP && c1 <= CAND_MAX) {
        C = (int)c1;                       // fast path: candidates complete
    } else {
        // ===== fallback (exact, rare): histogram -> threshold -> compact =====
        for (int i = tid; i < HBINS; i += TPB) shist[i] = 0u;
        __syncthreads();
        for (int r = gtid; r < n; r += gthreads)
            atomicAdd(&shist[fkey(g_y[r]) >> HSHIFT], 1u);
        __syncthreads();
        for (int i = tid; i < HBINS; i += TPB) {
            unsigned int v = shist[i];
            if (v) atomicAdd(&g_hist[i], v);
        }
        grid_bar(nb);
        // threshold bin (every block, redundant)
        {
            const uint4* h4 = reinterpret_cast<const uint4*>(g_hist) + tid * 4;
            uint4 a = h4[0], b = h4[1], c = h4[2], d = h4[3];
            unsigned int part = a.x + a.y + a.z + a.w + b.x + b.y + b.z + b.w
                              + c.x + c.y + c.z + c.w + d.x + d.y + d.z + d.w;
            unsigned int s = part;
            #pragma unroll
            for (int off = 1; off < 32; off <<= 1) {
                unsigned int v = __shfl_down_sync(0xffffffffu, s, off);
                if (lane + off < 32) s += v;
            }
            if (lane == 0) swt[wib] = s;
            __syncthreads();
            if (tid < 16) {
                unsigned int acc = 0;
                for (int i = tid + 1; i < 16; i++) acc += swt[i];
                saf[tid] = acc;
            }
            __syncthreads();
            unsigned int incl = s + saf[wib];
            unsigned int nxt = incl - part;
            if (incl >= KTOP && nxt < KTOP) {
                unsigned int acc = nxt;
                for (int bi = tid * 16 + 15; bi >= tid * 16; bi--) {
                    acc += g_hist[bi];
                    if (acc >= KTOP) { s_tbin = (unsigned int)bi; break; }
                }
            }
            __syncthreads();
        }
        // compact using exact bin threshold
        {
            unsigned int tb = s_tbin;
            for (int r = gtid; r < n; r += gthreads) {
                float y = g_y[r];
                if ((fkey(y) >> HSHIFT) >= tb) push_cand(y, r, &g_cnt2);
            }
        }
        grid_bar(nb);
        unsigned int c2 = g_cnt2;
        if (tid == 0) {
            if (atomicAdd(&g_done, 1u) + 1u == (unsigned int)nb) {
                g_cnt2 = 0u;
                g_done = 0u;
            }
        }
        for (int i = tid; i < HBINS; i += TPB) shist[i] = 0u;   // clear union before sk use
        for (int i = gtid; i < HBINS; i += gthreads) g_hist[i] = 0u;
        C = (int)min(c2, (unsigned int)CAND_MAX);
        grid_bar(nb);      // hist reads done & cand writes visible before rank
    }

    // ---- rank + gather + write (fused): 64 candidates/block ----
    {
        int nactive = (C + 63) >> 6;
        if (blockIdx.x < nactive) {
            for (int i = tid; i < C; i += TPB) sk[i] = g_cand[i];
            __syncthreads();
            int j = tid & 63;
            int seg = tid >> 6;            // 8 segments
            int jg = blockIdx.x * 64 + j;
            unsigned long long pk = (jg < C) ? sk[jg] : ~0ull;
            int segsz = (C + 7) >> 3;
            int lo = seg * segsz;
            int hi = lo + segsz; if (hi > C) hi = C;
            int part = 0;
            int i = lo;
            for (; i + 4 <= hi; i += 4) {
                part += (sk[i + 0] > pk);
                part += (sk[i + 1] > pk);
                part += (sk[i + 2] > pk);
                part += (sk[i + 3] > pk);
            }
            for (; i < hi; i++) part += (sk[i] > pk);
            ss[tid] = (unsigned int)part;
            __syncthreads();
            if (tid < 64) {
                int rk = -1, idx = 0;
                float tv = 0.f;
                if (jg < C) {
                    int rank = (int)(ss[tid] + ss[tid + 64] + ss[tid + 128] +
                                     ss[tid + 192] + ss[tid + 256] + ss[tid + 320] +
                                     ss[tid + 384] + ss[tid + 448]);
                    if (rank < KTOP) {
                        unsigned int key = (unsigned int)(pk >> 32);
                        unsigned int u = (key & 0x80000000u) ? (key ^ 0x80000000u) : ~key;
                        rk = rank;
                        idx = (int)(~(unsigned int)(pk & 0xFFFFFFFFull));
                        tv = tanhf(__uint_as_float(u));
                    }
                }
                s_rk[tid] = rk;
                s_ridx[tid] = idx;
                s_rt[tid] = tv;
            }
            __syncthreads();
            // gather + write: 8 threads per candidate
            {
                int c = tid >> 3;
                int sg = tid & 7;
                int rk = s_rk[c];
                if (rk >= 0) {
                    int idx = s_ridx[c];
                    float tv = s_rt[c];
                    const float4* xr = x4 + (size_t)idx * 32 + sg;
                    float4* orow = reinterpret_cast<float4*>(out) + (size_t)rk * 32 + sg;
                    float4 v0 = xr[0], v1 = xr[8], v2 = xr[16], v3 = xr[24];
                    orow[0]  = make_float4(v0.x * tv, v0.y * tv, v0.z * tv, v0.w * tv);
                    orow[8]  = make_float4(v1.x * tv, v1.y * tv, v1.z * tv, v1.w * tv);
                    orow[16] = make_float4(v2.x * tv, v2.y * tv, v2.z * tv, v2.w * tv);
                    orow[24] = make_float4(v3.x * tv, v3.y * tv, v3.z * tv, v3.w * tv);
                }
            }
        }
    }
}

extern "C" void kernel_launch(void* const* d_in, const int* in_sizes, int n_in,
                              void* d_out, int out_size) {
    const float* x = (const float*)d_in[0];
    const float* p = (const float*)d_in[1];
    int n = in_sizes[0] / DD;

    int dev = 0;
    cudaGetDevice(&dev);
    int sm = 0;
    cudaDeviceGetAttribute(&sm, cudaDevAttrMultiProcessorCount, dev);
    int bpsm = 0;
    cudaOccupancyMaxActiveBlocksPerMultiprocessor(&bpsm, mega, TPB, 0);
    if (bpsm < 1) bpsm = 1;
    int nb = sm * bpsm;
    if (nb > NB_CAP) nb = NB_CAP;

    mega<<<nb, TPB>>>(x, p, (float*)d_out, n, nb);
}

// round 13
// speedup vs baseline: 1.0149x; 1.0046x over previous
#include <cuda_runtime.h>
#include <cstdint>

#define KTOP 2048
#define DD 128
#define HBINS 8192            // 13-bit key prefix (fallback path)
#define HSHIFT 19
#define CAND_MAX 6144
#define TS_VAL 2.42f          // speculative threshold; exact path verifies bounds
#define TPB 256
#define NB_CAP 1024

// ---- static scratch (no allocations allowed) ----
__device__ unsigned int g_hist[HBINS];          // fallback only (kept zeroed)
__device__ float g_y[500224];
__device__ unsigned int g_cnt;
__device__ unsigned int g_cnt2;
__device__ unsigned int g_done;
__device__ __align__(16) unsigned long long g_cand[CAND_MAX];
__device__ unsigned int g_bar_count;
__device__ volatile unsigned int g_bar_gen;

// monotonic unsigned key for f32 ordering
__device__ __forceinline__ unsigned int fkey(float f) {
    unsigned int u = __float_as_uint(f);
    return (u & 0x80000000u) ? ~u : (u | 0x80000000u);
}
__device__ __forceinline__ float dot4(float4 a, float4 b) {
    return a.x * b.x + a.y * b.y + a.z * b.z + a.w * b.w;
}

// software grid barrier (all blocks co-resident by construction)
__device__ __forceinline__ void grid_bar(int nb) {
    __threadfence();
    __syncthreads();
    if (threadIdx.x == 0) {
        unsigned int gen = g_bar_gen;
        if (atomicAdd(&g_bar_count, 1u) == (unsigned int)(nb - 1)) {
            g_bar_count = 0u;
            __threadfence();
            g_bar_gen = gen + 1u;
        } else {
            while (g_bar_gen == gen) { __nanosleep(64); }
        }
    }
    __syncthreads();
}

__device__ __forceinline__ void push_cand(float y, int i, unsigned int* cnt) {
    unsigned int key = fkey(y);
    unsigned int pos = atomicAdd(cnt, 1u);
    if (pos < CAND_MAX) {
        // value-descending major, index-ascending minor
        g_cand[pos] = ((unsigned long long)key << 32) |
                      (unsigned long long)(~(unsigned int)i);
    }
}

// 4-row group: each 8-lane subgroup handles one row; 4 float4 loads per lane
#define LOAD4(c0,c1,c2,c3, r0) do {                                          \
    const float4* _xp = x4 + (size_t)((r0) + grp) * 32 + l8;                 \
    c0 = __ldcs(_xp + 0);  c1 = __ldcs(_xp + 8);                             \
    c2 = __ldcs(_xp + 16); c3 = __ldcs(_xp + 24);                            \
} while (0)

#define COMP4(c0,c1,c2,c3, r0) do {                                          \
    float _s = (dot4(c0, q0) + dot4(c1, q1)) + (dot4(c2, q2) + dot4(c3, q3));\
    _s += __shfl_xor_sync(0xffffffffu, _s, 1);                               \
    _s += __shfl_xor_sync(0xffffffffu, _s, 2);                               \
    _s += __shfl_xor_sync(0xffffffffu, _s, 4);                               \
    if (l8 == 0) {                                                           \
        int _r = (r0) + grp;                                                 \
        float _y = _s * inv;                                                 \
        g_y[_r] = _y;                                                        \
        if (_y >= TS_VAL) push_cand(_y, _r, &g_cnt);                         \
    }                                                                        \
} while (0)

__global__ void __launch_bounds__(TPB, 3)
mega(const float* __restrict__ x, const float* __restrict__ p,
     float* __restrict__ out, int n, int nb)
{
    const int tid = threadIdx.x;
    const int lane = tid & 31;
    const int l8 = lane & 7;
    const int grp = lane >> 3;
    const int wib = tid >> 5;              // warp in block (8)
    const int gtid = blockIdx.x * TPB + tid;
    const int gthreads = nb * TPB;
    const int wid = gtid >> 5;
    const int nw = gthreads >> 5;

    // union: rank keys (6144 u64 = 48 KB) / fallback smem hist (8192 u32 = 32 KB)
    // NOTE: 48 KB smem at 3 blocks/SM would not fit -> but phase-1 uses no smem
    // beyond this static buffer; occupancy target is reg-driven. smem per block
    // must stay <= ~75 KB/3 = 25 KB... so shrink the union: cap sk at CAND via
    // 3072-entry smem window? Instead: sk uses 24 KB (3072 keys) + strided pass.
    __shared__ __align__(16) unsigned char sbuf[24576];   // 3072 u64 / 6144 u32
    unsigned long long* sk = reinterpret_cast<unsigned long long*>(sbuf);
    unsigned int* shist = reinterpret_cast<unsigned int*>(sbuf);   // 6144 bins/pass
    __shared__ unsigned int ss[TPB];
    __shared__ unsigned int swt[8], saf[8];
    __shared__ unsigned int s_tbin;
    __shared__ int s_rk[64];
    __shared__ int s_ridx[64];
    __shared__ float s_rt[64];

    // ---- phase 0: norm (per-warp, registers only) ----
    const float4* __restrict__ p4 = reinterpret_cast<const float4*>(p);
    float4 q0 = p4[l8], q1 = p4[l8 + 8], q2 = p4[l8 + 16], q3 = p4[l8 + 24];
    float s2 = (dot4(q0, q0) + dot4(q1, q1)) + (dot4(q2, q2) + dot4(q3, q3));
    s2 += __shfl_xor_sync(0xffffffffu, s2, 1);
    s2 += __shfl_xor_sync(0xffffffffu, s2, 2);
    s2 += __shfl_xor_sync(0xffffffffu, s2, 4);
    const float inv = 1.0f / sqrtf(s2);

    // ---- phase 1: ping-pong pipelined coalesced dot + speculative push ----
    const float4* __restrict__ x4 = reinterpret_cast<const float4*>(x);
    const int n4a = n & ~3;
    const int stride4 = nw * 4;
    {
        const int wbase = wid * 4;
        int niter = (wbase < n4a) ? ((n4a - 1 - wbase) / stride4 + 1) : 0;
        float4 a0, a1, a2, a3;
        float4 b0, b1, b2, b3;
        if (niter > 0) LOAD4(a0, a1, a2, a3, wbase);
        int i = 0;
        for (; i + 2 <= niter; i += 2) {
            int rcur = wbase + i * stride4;
            int rmid = rcur + stride4;
            LOAD4(b0, b1, b2, b3, rmid);
            COMP4(a0, a1, a2, a3, rcur);
            if (i + 2 < niter) {
                int rnxt = rmid + stride4;
                LOAD4(a0, a1, a2, a3, rnxt);
            }
            COMP4(b0, b1, b2, b3, rmid);
        }
        if (i < niter) {
            COMP4(a0, a1, a2, a3, wbase + i * stride4);
        }
    }
    // tail rows [n4a, n): block 0 / warp 0, full-width dot
    if (blockIdx.x == 0 && tid < 32 && n4a < n) {
        float4 pl = p4[lane];
        for (int r = n4a; r < n; r++) {
            float4 v = x4[(size_t)r * 32 + lane];
            float s = dot4(v, pl);
            #pragma unroll
            for (int o = 16; o; o >>= 1) s += __shfl_xor_sync(0xffffffffu, s, o);
            if (lane == 0) {
                float y = s * inv;
                g_y[r] = y;
                if (y >= TS_VAL) push_cand(y, r, &g_cnt);
            }
        }
    }
    grid_bar(nb);

    unsigned int c1 = g_cnt;
    // handshake: reset g_cnt once every block has read it
    if (tid == 0) {
        if (atomicAdd(&g_done, 1u) + 1u == (unsigned int)nb) {
            g_cnt = 0u;
            g_done = 0u;
        }
    }

    int C;
    if (c1 >= KTOP && c1 <= CAND_MAX) {
        C = (int)c1;                       // fast path: candidates complete
    } else {
        // ===== fallback (exact, rare): histogram -> threshold -> compact =====
        // two passes of 6144 smem bins would complicate; use global hist directly
        // (fallback is rare; performance there is irrelevant)
        for (int r = gtid; r < n; r += gthreads)
            atomicAdd(&g_hist[fkey(g_y[r]) >> HSHIFT], 1u);
        grid_bar(nb);
        // threshold bin (every block, redundant): 32 bins/thread
        {
            const uint4* h4 = reinterpret_cast<const uint4*>(g_hist) + tid * 8;
            unsigned int part = 0;
            #pragma unroll
            for (int i = 0; i < 8; i++) {
                uint4 a = h4[i];
                part += a.x + a.y + a.z + a.w;
            }
            unsigned int s = part;
            #pragma unroll
            for (int off = 1; off < 32; off <<= 1) {
                unsigned int v = __shfl_down_sync(0xffffffffu, s, off);
                if (lane + off < 32) s += v;
            }
            if (lane == 0) swt[wib] = s;
            __syncthreads();
            if (tid < 8) {
                unsigned int acc = 0;
                for (int i = tid + 1; i < 8; i++) acc += swt[i];
                saf[tid] = acc;
            }
            __syncthreads();
            unsigned int incl = s + saf[wib];
            unsigned int nxt = incl - part;
            if (incl >= KTOP && nxt < KTOP) {
                unsigned int acc = nxt;
                for (int bi = tid * 32 + 31; bi >= tid * 32; bi--) {
                    acc += g_hist[bi];
                    if (acc >= KTOP) { s_tbin = (unsigned int)bi; break; }
                }
            }
            __syncthreads();
        }
        // compact using exact bin threshold
        {
            unsigned int tb = s_tbin;
            for (int r = gtid; r < n; r += gthreads) {
                float y = g_y[r];
                if ((fkey(y) >> HSHIFT) >= tb) push_cand(y, r, &g_cnt2);
            }
        }
        grid_bar(nb);
        unsigned int c2 = g_cnt2;
        if (tid == 0) {
            if (atomicAdd(&g_done, 1u) + 1u == (unsigned int)nb) {
                g_cnt2 = 0u;
                g_done = 0u;
            }
        }
        for (int i = gtid; i < HBINS; i += gthreads) g_hist[i] = 0u;
        C = (int)min(c2, (unsigned int)CAND_MAX);
        grid_bar(nb);      // hist reads done & cand writes visible before rank
    }

    // ---- rank + gather + write (fused): 64 candidates/block ----
    // smem key cache holds 3072 keys; scan runs in up to 2 windows.
    {
        int nactive = (C + 63) >> 6;
        if (blockIdx.x < nactive) {
            int jg = blockIdx.x * 64 + (tid & 63);
            unsigned long long pk = (jg < C) ? g_cand[jg] : ~0ull;
            int seg = tid >> 6;            // 4 segments of each window
            int rank = 0;
            for (int w0 = 0; w0 < C; w0 += 3072) {
                int wlen = C - w0; if (wlen > 3072) wlen = 3072;
                __syncthreads();
                for (int i = tid; i < wlen; i += TPB) sk[i] = g_cand[w0 + i];
                __syncthreads();
                int segsz = (wlen + 3) >> 2;
                int lo = seg * segsz;
                int hi = lo + segsz; if (hi > wlen) hi = wlen;
                int part = 0;
                int i = lo;
                for (; i + 4 <= hi; i += 4) {
                    part += (sk[i + 0] > pk);
                    part += (sk[i + 1] > pk);
                    part += (sk[i + 2] > pk);
                    part += (sk[i + 3] > pk);
                }
                for (; i < hi; i++) part += (sk[i] > pk);
                ss[tid] = (unsigned int)part;
                __syncthreads();
                if (tid < 64)
                    rank += (int)(ss[tid] + ss[tid + 64] + ss[tid + 128] + ss[tid + 192]);
            }
            if (tid < 64) {
                int rk = -1, idx = 0;
                float tv = 0.f;
                if (jg < C && rank < KTOP) {
                    unsigned int key = (unsigned int)(pk >> 32);
                    unsigned int u = (key & 0x80000000u) ? (key ^ 0x80000000u) : ~key;
                    rk = rank;
                    idx = (int)(~(unsigned int)(pk & 0xFFFFFFFFull));
                    tv = tanhf(__uint_as_float(u));
                }
                s_rk[tid] = rk;
                s_ridx[tid] = idx;
                s_rt[tid] = tv;
            }
            __syncthreads();
            // gather + write: 8 threads per candidate, 2 passes of 32
            #pragma unroll
            for (int c0 = 0; c0 < 64; c0 += 32) {
                int c = c0 + (tid >> 3);
                int sg = tid & 7;
                int rk = s_rk[c];
                if (rk >= 0) {
                    int idx = s_ridx[c];
                    float tv = s_rt[c];
                    const float4* xr = x4 + (size_t)idx * 32 + sg;
                    float4* orow = reinterpret_cast<float4*>(out) + (size_t)rk * 32 + sg;
                    float4 v0 = xr[0], v1 = xr[8], v2 = xr[16], v3 = xr[24];
                    orow[0]  = make_float4(v0.x * tv, v0.y * tv, v0.z * tv, v0.w * tv);
                    orow[8]  = make_float4(v1.x * tv, v1.y * tv, v1.z * tv, v1.w * tv);
                    orow[16] = make_float4(v2.x * tv, v2.y * tv, v2.z * tv, v2.w * tv);
                    orow[24] = make_float4(v3.x * tv, v3.y * tv, v3.z * tv, v3.w * tv);
                }
            }
        }
    }
}

extern "C" void kernel_launch(void* const* d_in, const int* in_sizes, int n_in,
                              void* d_out, int out_size) {
    const float* x = (const float*)d_in[0];
    const float* p = (const float*)d_in[1];
    int n = in_sizes[0] / DD;

    int dev = 0;
    cudaGetDevice(&dev);
    int sm = 0;
    cudaDeviceGetAttribute(&sm, cudaDevAttrMultiProcessorCount, dev);
    int bpsm = 0;
    cudaOccupancyMaxActiveBlocksPerMultiprocessor(&bpsm, mega, TPB, 0);
    if (bpsm < 1) bpsm = 1;
    int nb = sm * bpsm;
    if (nb > NB_CAP) nb = NB_CAP;

    mega<<<nb, TPB>>>(x, p, (float*)d_out, n, nb);
}

// round 14
// speedup vs baseline: 1.1253x; 1.1088x over previous
#include <cuda_runtime.h>
#include <cstdint>

#define KTOP 2048
#define DD 128
#define HBINS 8192            // 13-bit key prefix (fallback path)
#define HSHIFT 19
#define CAND_MAX 6144
#define TS_VAL 2.42f          // speculative threshold; exact path verifies bounds
#define TPB 512
#define NB_CAP 1024

// ---- static scratch (no allocations allowed) ----
__device__ unsigned int g_hist[HBINS];          // fallback only (kept zeroed)
__device__ float g_y[500224];
__device__ unsigned int g_cnt;
__device__ unsigned int g_cnt2;
__device__ unsigned int g_done;
__device__ __align__(16) unsigned long long g_cand[CAND_MAX];
__device__ unsigned int g_bar_count;
__device__ volatile unsigned int g_bar_gen;

// monotonic unsigned key for f32 ordering
__device__ __forceinline__ unsigned int fkey(float f) {
    unsigned int u = __float_as_uint(f);
    return (u & 0x80000000u) ? ~u : (u | 0x80000000u);
}
__device__ __forceinline__ float dot4(float4 a, float4 b) {
    return a.x * b.x + a.y * b.y + a.z * b.z + a.w * b.w;
}

// software grid barrier (all blocks co-resident by construction)
__device__ __forceinline__ void grid_bar(int nb) {
    __threadfence();
    __syncthreads();
    if (threadIdx.x == 0) {
        unsigned int gen = g_bar_gen;
        if (atomicAdd(&g_bar_count, 1u) == (unsigned int)(nb - 1)) {
            g_bar_count = 0u;
            __threadfence();
            g_bar_gen = gen + 1u;
        } else {
            while (g_bar_gen == gen) { __nanosleep(64); }
        }
    }
    __syncthreads();
}

__device__ __forceinline__ void push_cand(float y, int i, unsigned int* cnt) {
    unsigned int key = fkey(y);
    unsigned int pos = atomicAdd(cnt, 1u);
    if (pos < CAND_MAX) {
        // value-descending major, index-ascending minor
        g_cand[pos] = ((unsigned long long)key << 32) |
                      (unsigned long long)(~(unsigned int)i);
    }
}

__global__ void __launch_bounds__(TPB, 2)
mega(const float* __restrict__ x, const float* __restrict__ p,
     float* __restrict__ out, int n, int nb)
{
    const int tid = threadIdx.x;
    const int lane = tid & 31;
    const int l8 = lane & 7;
    const int grp = lane >> 3;
    const int wib = tid >> 5;
    const int gtid = blockIdx.x * TPB + tid;
    const int gthreads = nb * TPB;
    const int wid = gtid >> 5;
    const int nw = gthreads >> 5;

    // union: rank keys (6144 u64 = 48 KB) / fallback smem hist (8192 u32 = 32 KB)
    __shared__ __align__(16) unsigned char sbuf[CAND_MAX * 8];
    unsigned long long* sk = reinterpret_cast<unsigned long long*>(sbuf);
    unsigned int* shist = reinterpret_cast<unsigned int*>(sbuf);
    __shared__ unsigned int ss[TPB];
    __shared__ unsigned int swt[16], saf[16];
    __shared__ unsigned int s_tbin;
    __shared__ int s_rk[16];
    __shared__ int s_ridx[16];
    __shared__ float s_rt[16];

    // ---- phase 0: norm (per-warp, registers only) ----
    const float4* __restrict__ p4 = reinterpret_cast<const float4*>(p);
    float4 q0 = p4[l8], q1 = p4[l8 + 8], q2 = p4[l8 + 16], q3 = p4[l8 + 24];
    float s2 = (dot4(q0, q0) + dot4(q1, q1)) + (dot4(q2, q2) + dot4(q3, q3));
    s2 += __shfl_xor_sync(0xffffffffu, s2, 1);
    s2 += __shfl_xor_sync(0xffffffffu, s2, 2);
    s2 += __shfl_xor_sync(0xffffffffu, s2, 4);
    const float inv = 1.0f / sqrtf(s2);

    // ---- phase 1: coalesced dot + immediate speculative candidate push ----
    const float4* __restrict__ x4 = reinterpret_cast<const float4*>(x);
    const int n8 = n & ~7;
    for (int r0 = wid * 8; r0 < n8; r0 += nw * 8) {
        int rA = r0 + grp;
        const float4* xa = x4 + (size_t)rA * 32 + l8;
        const float4* xb = xa + 4 * 32;
        float4 a0 = __ldcs(xa + 0), a1 = __ldcs(xa + 8),
               a2 = __ldcs(xa + 16), a3 = __ldcs(xa + 24);
        float4 b0 = __ldcs(xb + 0), b1 = __ldcs(xb + 8),
               b2 = __ldcs(xb + 16), b3 = __ldcs(xb + 24);
        float sA = (dot4(a0, q0) + dot4(a1, q1)) + (dot4(a2, q2) + dot4(a3, q3));
        float sB = (dot4(b0, q0) + dot4(b1, q1)) + (dot4(b2, q2) + dot4(b3, q3));
        sA += __shfl_xor_sync(0xffffffffu, sA, 1);
        sB += __shfl_xor_sync(0xffffffffu, sB, 1);
        sA += __shfl_xor_sync(0xffffffffu, sA, 2);
        sB += __shfl_xor_sync(0xffffffffu, sB, 2);
        sA += __shfl_xor_sync(0xffffffffu, sA, 4);
        sB += __shfl_xor_sync(0xffffffffu, sB, 4);
        if (l8 == 0) {
            float yA = sA * inv;
            float yB = sB * inv;
            g_y[rA] = yA;
            g_y[rA + 4] = yB;
            if (yA >= TS_VAL) push_cand(yA, rA, &g_cnt);
            if (yB >= TS_VAL) push_cand(yB, rA + 4, &g_cnt);
        }
    }
    // tail rows [n8, n): block 0 / warp 0
    if (blockIdx.x == 0 && tid < 32 && n8 < n) {
        float4 pl = p4[lane];
        for (int r = n8; r < n; r++) {
            float4 v = x4[(size_t)r * 32 + lane];
            float s = dot4(v, pl);
            #pragma unroll
            for (int o = 16; o; o >>= 1) s += __shfl_xor_sync(0xffffffffu, s, o);
            if (lane == 0) {
                float y = s * inv;
                g_y[r] = y;
                if (y >= TS_VAL) push_cand(y, r, &g_cnt);
            }
        }
    }
    grid_bar(nb);

    unsigned int c1 = g_cnt;
    // handshake: reset g_cnt once every block has read it
    if (tid == 0) {
        if (atomicAdd(&g_done, 1u) + 1u == (unsigned int)nb) {
            g_cnt = 0u;
            g_done = 0u;
        }
    }

    int C;
    if (c1 >= KTOP && c1 <= CAND_MAX) {
        C = (int)c1;                       // fast path: candidates complete
    } else {
        // ===== fallback (exact, rare): histogram -> threshold -> compact =====
        for (int i = tid; i < HBINS; i += TPB) shist[i] = 0u;
        __syncthreads();
        for (int r = gtid; r < n; r += gthreads)
            atomicAdd(&shist[fkey(g_y[r]) >> HSHIFT], 1u);
        __syncthreads();
        for (int i = tid; i < HBINS; i += TPB) {
            unsigned int v = shist[i];
            if (v) atomicAdd(&g_hist[i], v);
        }
        grid_bar(nb);
        // threshold bin (every block, redundant)
        {
            const uint4* h4 = reinterpret_cast<const uint4*>(g_hist) + tid * 4;
            uint4 a = h4[0], b = h4[1], c = h4[2], d = h4[3];
            unsigned int part = a.x + a.y + a.z + a.w + b.x + b.y + b.z + b.w
                              + c.x + c.y + c.z + c.w + d.x + d.y + d.z + d.w;
            unsigned int s = part;
            #pragma unroll
            for (int off = 1; off < 32; off <<= 1) {
                unsigned int v = __shfl_down_sync(0xffffffffu, s, off);
                if (lane + off < 32) s += v;
            }
            if (lane == 0) swt[wib] = s;
            __syncthreads();
            if (tid < 16) {
                unsigned int acc = 0;
                for (int i = tid + 1; i < 16; i++) acc += swt[i];
                saf[tid] = acc;
            }
            __syncthreads();
            unsigned int incl = s + saf[wib];
            unsigned int nxt = incl - part;
            if (incl >= KTOP && nxt < KTOP) {
                unsigned int acc = nxt;
                for (int bi = tid * 16 + 15; bi >= tid * 16; bi--) {
                    acc += g_hist[bi];
                    if (acc >= KTOP) { s_tbin = (unsigned int)bi; break; }
                }
            }
            __syncthreads();
        }
        // compact using exact bin threshold
        {
            unsigned int tb = s_tbin;
            for (int r = gtid; r < n; r += gthreads) {
                float y = g_y[r];
                if ((fkey(y) >> HSHIFT) >= tb) push_cand(y, r, &g_cnt2);
            }
        }
        grid_bar(nb);
        unsigned int c2 = g_cnt2;
        if (tid == 0) {
            if (atomicAdd(&g_done, 1u) + 1u == (unsigned int)nb) {
                g_cnt2 = 0u;
                g_done = 0u;
            }
        }
        for (int i = tid; i < HBINS; i += TPB) shist[i] = 0u;   // clear union before sk use
        for (int i = gtid; i < HBINS; i += gthreads) g_hist[i] = 0u;
        C = (int)min(c2, (unsigned int)CAND_MAX);
        grid_bar(nb);      // hist reads done & cand writes visible before rank
    }

    // ---- rank + gather + write (fused): 16 candidates/block, 32 segments ----
    {
        int nactive = (C + 15) >> 4;               // candidate groups of 16
        if (blockIdx.x < nactive) {
            // stage all keys once (C <= 6144 fits the 48 KB cache)
            for (int i = tid; i < C; i += TPB) sk[i] = g_cand[i];
            __syncthreads();

            const int j = tid & 15;                // candidate slot in group
            const int seg = tid >> 4;              // segment 0..31
            const int segsz = (C + 31) >> 5;
            const int lo = seg * segsz;
            int hi = lo + segsz; if (hi > C) hi = C;

            for (int g = blockIdx.x; g * 16 < C; g += nb) {
                int jg = g * 16 + j;
                unsigned long long pk = (jg < C) ? sk[jg] : ~0ull;
                int part = 0;
                int i = lo;
                for (; i + 4 <= hi; i += 4) {
                    part += (sk[i + 0] > pk);
                    part += (sk[i + 1] > pk);
                    part += (sk[i + 2] > pk);
                    part += (sk[i + 3] > pk);
                }
                for (; i < hi; i++) part += (sk[i] > pk);
                ss[tid] = (unsigned int)part;
                __syncthreads();
                if (tid < 16) {
                    int rk = -1, idx = 0;
                    float tv = 0.f;
                    if (jg < C) {
                        int rank = 0;
                        #pragma unroll
                        for (int s = 0; s < 32; s++) rank += (int)ss[s * 16 + tid];
                        if (rank < KTOP) {
                            unsigned int key = (unsigned int)(pk >> 32);
                            unsigned int u = (key & 0x80000000u) ? (key ^ 0x80000000u) : ~key;
                            rk = rank;
                            idx = (int)(~(unsigned int)(pk & 0xFFFFFFFFull));
                            tv = tanhf(__uint_as_float(u));
                        }
                    }
                    s_rk[tid] = rk;
                    s_ridx[tid] = idx;
                    s_rt[tid] = tv;
                }
                __syncthreads();
                // gather + write: 32 lanes per candidate, one float4 each
                {
                    int c = tid >> 5;              // 0..15
                    int rk = s_rk[c];
                    if (rk >= 0) {
                        int idx = s_ridx[c];
                        float tv = s_rt[c];
                        float4 v = x4[(size_t)idx * 32 + lane];
                        reinterpret_cast<float4*>(out)[(size_t)rk * 32 + lane] =
                            make_float4(v.x * tv, v.y * tv, v.z * tv, v.w * tv);
                    }
                }
                __syncthreads();
            }
        }
    }
}

extern "C" void kernel_launch(void* const* d_in, const int* in_sizes, int n_in,
                              void* d_out, int out_size) {
    const float* x = (const float*)d_in[0];
    const float* p = (const float*)d_in[1];
    int n = in_sizes[0] / DD;

    int dev = 0;
    cudaGetDevice(&dev);
    int sm = 0;
    cudaDeviceGetAttribute(&sm, cudaDevAttrMultiProcessorCount, dev);
    int bpsm = 0;
    cudaOccupancyMaxActiveBlocksPerMultiprocessor(&bpsm, mega, TPB, 0);
    if (bpsm < 1) bpsm = 1;
    int nb = sm * bpsm;
    if (nb > NB_CAP) nb = NB_CAP;

    mega<<<nb, TPB>>>(x, p, (float*)d_out, n, nb);
}

// round 15
// speedup vs baseline: 1.1825x; 1.0508x over previous
#include <cuda_runtime.h>
#include <cstdint>

#define KTOP 2048
#define DD 128
#define HBINS 8192            // 13-bit key prefix (fallback path)
#define HSHIFT 19
#define CAND_MAX 6144
#define TS_VAL 2.55f          // speculative threshold; exact fallback verifies bounds
#define TPB 512
#define NB_CAP 1024

// ---- static scratch (no allocations allowed) ----
__device__ unsigned int g_hist[HBINS];          // fallback only (kept zeroed)
__device__ float g_y[500224];                   // fallback only
__device__ unsigned int g_cnt;
__device__ unsigned int g_cnt2;
__device__ unsigned int g_done;
__device__ __align__(16) unsigned long long g_cand[CAND_MAX];
__device__ unsigned int g_bar_count;
__device__ volatile unsigned int g_bar_gen;

// monotonic unsigned key for f32 ordering
__device__ __forceinline__ unsigned int fkey(float f) {
    unsigned int u = __float_as_uint(f);
    return (u & 0x80000000u) ? ~u : (u | 0x80000000u);
}
__device__ __forceinline__ float dot4(float4 a, float4 b) {
    return a.x * b.x + a.y * b.y + a.z * b.z + a.w * b.w;
}

// software grid barrier (all blocks co-resident by construction)
__device__ __forceinline__ void grid_bar(int nb) {
    __threadfence();
    __syncthreads();
    if (threadIdx.x == 0) {
        unsigned int gen = g_bar_gen;
        if (atomicAdd(&g_bar_count, 1u) == (unsigned int)(nb - 1)) {
            g_bar_count = 0u;
            __threadfence();
            g_bar_gen = gen + 1u;
        } else {
            while (g_bar_gen == gen) { __nanosleep(64); }
        }
    }
    __syncthreads();
}

__device__ __forceinline__ void push_cand(float y, int i, unsigned int* cnt) {
    unsigned int key = fkey(y);
    unsigned int pos = atomicAdd(cnt, 1u);
    if (pos < CAND_MAX) {
        // value-descending major, index-ascending minor
        g_cand[pos] = ((unsigned long long)key << 32) |
                      (unsigned long long)(~(unsigned int)i);
    }
}

__global__ void __launch_bounds__(TPB, 2)
mega(const float* __restrict__ x, const float* __restrict__ p,
     float* __restrict__ out, int n, int nb)
{
    const int tid = threadIdx.x;
    const int lane = tid & 31;
    const int l8 = lane & 7;
    const int grp = lane >> 3;
    const int wib = tid >> 5;
    const int gtid = blockIdx.x * TPB + tid;
    const int gthreads = nb * TPB;
    const int wid = gtid >> 5;
    const int nw = gthreads >> 5;

    // union: rank keys (6144 u64 = 48 KB) / fallback smem hist (8192 u32 = 32 KB)
    __shared__ __align__(16) unsigned char sbuf[CAND_MAX * 8];
    unsigned long long* sk = reinterpret_cast<unsigned long long*>(sbuf);
    unsigned int* shist = reinterpret_cast<unsigned int*>(sbuf);
    __shared__ unsigned int ss[TPB];
    __shared__ unsigned int swt[16], saf[16];
    __shared__ unsigned int s_tbin;
    __shared__ int s_rk[16];
    __shared__ int s_ridx[16];
    __shared__ float s_rt[16];

    // ---- phase 0: norm (per-warp, registers only) ----
    const float4* __restrict__ p4 = reinterpret_cast<const float4*>(p);
    float4 q0 = p4[l8], q1 = p4[l8 + 8], q2 = p4[l8 + 16], q3 = p4[l8 + 24];
    float s2 = (dot4(q0, q0) + dot4(q1, q1)) + (dot4(q2, q2) + dot4(q3, q3));
    s2 += __shfl_xor_sync(0xffffffffu, s2, 1);
    s2 += __shfl_xor_sync(0xffffffffu, s2, 2);
    s2 += __shfl_xor_sync(0xffffffffu, s2, 4);
    const float inv = 1.0f / sqrtf(s2);

    // ---- phase 1: coalesced dot + speculative candidate push (no y store) ----
    const float4* __restrict__ x4 = reinterpret_cast<const float4*>(x);
    const int n8 = n & ~7;
    for (int r0 = wid * 8; r0 < n8; r0 += nw * 8) {
        int rA = r0 + grp;
        const float4* xa = x4 + (size_t)rA * 32 + l8;
        const float4* xb = xa + 4 * 32;
        float4 a0 = __ldcs(xa + 0), a1 = __ldcs(xa + 8),
               a2 = __ldcs(xa + 16), a3 = __ldcs(xa + 24);
        float4 b0 = __ldcs(xb + 0), b1 = __ldcs(xb + 8),
               b2 = __ldcs(xb + 16), b3 = __ldcs(xb + 24);
        float sA = (dot4(a0, q0) + dot4(a1, q1)) + (dot4(a2, q2) + dot4(a3, q3));
        float sB = (dot4(b0, q0) + dot4(b1, q1)) + (dot4(b2, q2) + dot4(b3, q3));
        sA += __shfl_xor_sync(0xffffffffu, sA, 1);
        sB += __shfl_xor_sync(0xffffffffu, sB, 1);
        sA += __shfl_xor_sync(0xffffffffu, sA, 2);
        sB += __shfl_xor_sync(0xffffffffu, sB, 2);
        sA += __shfl_xor_sync(0xffffffffu, sA, 4);
        sB += __shfl_xor_sync(0xffffffffu, sB, 4);
        if (l8 == 0) {
            float yA = sA * inv;
            float yB = sB * inv;
            if (yA >= TS_VAL) push_cand(yA, rA, &g_cnt);
            if (yB >= TS_VAL) push_cand(yB, rA + 4, &g_cnt);
        }
    }
    // tail rows [n8, n): block 0 / warp 0
    if (blockIdx.x == 0 && tid < 32 && n8 < n) {
        float4 pl = p4[lane];
        for (int r = n8; r < n; r++) {
            float4 v = x4[(size_t)r * 32 + lane];
            float s = dot4(v, pl);
            #pragma unroll
            for (int o = 16; o; o >>= 1) s += __shfl_xor_sync(0xffffffffu, s, o);
            if (lane == 0) {
                float y = s * inv;
                if (y >= TS_VAL) push_cand(y, r, &g_cnt);
            }
        }
    }
    grid_bar(nb);

    unsigned int c1 = g_cnt;
    // handshake: reset g_cnt once every block has read it
    if (tid == 0) {
        if (atomicAdd(&g_done, 1u) + 1u == (unsigned int)nb) {
            g_cnt = 0u;
            g_done = 0u;
        }
    }

    int C;
    if (c1 >= KTOP && c1 <= CAND_MAX) {
        C = (int)c1;                       // fast path: candidates complete
    } else {
        // ===== fallback (exact, rare): recompute y -> histogram -> compact =====
        // 1) materialize all y into g_y
        for (int r0 = wid * 8; r0 < n8; r0 += nw * 8) {
            int rA = r0 + grp;
            const float4* xa = x4 + (size_t)rA * 32 + l8;
            const float4* xb = xa + 4 * 32;
            float4 a0 = xa[0], a1 = xa[8], a2 = xa[16], a3 = xa[24];
            float4 b0 = xb[0], b1 = xb[8], b2 = xb[16], b3 = xb[24];
            float sA = (dot4(a0, q0) + dot4(a1, q1)) + (dot4(a2, q2) + dot4(a3, q3));
            float sB = (dot4(b0, q0) + dot4(b1, q1)) + (dot4(b2, q2) + dot4(b3, q3));
            sA += __shfl_xor_sync(0xffffffffu, sA, 1);
            sB += __shfl_xor_sync(0xffffffffu, sB, 1);
            sA += __shfl_xor_sync(0xffffffffu, sA, 2);
            sB += __shfl_xor_sync(0xffffffffu, sB, 2);
            sA += __shfl_xor_sync(0xffffffffu, sA, 4);
            sB += __shfl_xor_sync(0xffffffffu, sB, 4);
            if (l8 == 0) {
                g_y[rA] = sA * inv;
                g_y[rA + 4] = sB * inv;
            }
        }
        if (blockIdx.x == 0 && tid < 32 && n8 < n) {
            float4 pl = p4[lane];
            for (int r = n8; r < n; r++) {
                float4 v = x4[(size_t)r * 32 + lane];
                float s = dot4(v, pl);
                #pragma unroll
                for (int o = 16; o; o >>= 1) s += __shfl_xor_sync(0xffffffffu, s, o);
                if (lane == 0) g_y[r] = s * inv;
            }
        }
        grid_bar(nb);
        // 2) histogram
        for (int i = tid; i < HBINS; i += TPB) shist[i] = 0u;
        __syncthreads();
        for (int r = gtid; r < n; r += gthreads)
            atomicAdd(&shist[fkey(g_y[r]) >> HSHIFT], 1u);
        __syncthreads();
        for (int i = tid; i < HBINS; i += TPB) {
            unsigned int v = shist[i];
            if (v) atomicAdd(&g_hist[i], v);
        }
        grid_bar(nb);
        // 3) threshold bin (every block, redundant)
        {
            const uint4* h4 = reinterpret_cast<const uint4*>(g_hist) + tid * 4;
            uint4 a = h4[0], b = h4[1], c = h4[2], d = h4[3];
            unsigned int part = a.x + a.y + a.z + a.w + b.x + b.y + b.z + b.w
                              + c.x + c.y + c.z + c.w + d.x + d.y + d.z + d.w;
            unsigned int s = part;
            #pragma unroll
            for (int off = 1; off < 32; off <<= 1) {
                unsigned int v = __shfl_down_sync(0xffffffffu, s, off);
                if (lane + off < 32) s += v;
            }
            if (lane == 0) swt[wib] = s;
            __syncthreads();
            if (tid < 16) {
                unsigned int acc = 0;
                for (int i = tid + 1; i < 16; i++) acc += swt[i];
                saf[tid] = acc;
            }
            __syncthreads();
            unsigned int incl = s + saf[wib];
            unsigned int nxt = incl - part;
            if (incl >= KTOP && nxt < KTOP) {
                unsigned int acc = nxt;
                for (int bi = tid * 16 + 15; bi >= tid * 16; bi--) {
                    acc += g_hist[bi];
                    if (acc >= KTOP) { s_tbin = (unsigned int)bi; break; }
                }
            }
            __syncthreads();
        }
        // 4) compact using exact bin threshold
        {
            unsigned int tb = s_tbin;
            for (int r = gtid; r < n; r += gthreads) {
                float y = g_y[r];
                if ((fkey(y) >> HSHIFT) >= tb) push_cand(y, r, &g_cnt2);
            }
        }
        grid_bar(nb);
        unsigned int c2 = g_cnt2;
        if (tid == 0) {
            if (atomicAdd(&g_done, 1u) + 1u == (unsigned int)nb) {
                g_cnt2 = 0u;
                g_done = 0u;
            }
        }
        for (int i = tid; i < HBINS; i += TPB) shist[i] = 0u;   // clear union before sk use
        for (int i = gtid; i < HBINS; i += gthreads) g_hist[i] = 0u;
        C = (int)min(c2, (unsigned int)CAND_MAX);
        grid_bar(nb);      // hist reads done & cand writes visible before rank
    }

    // ---- rank + gather + write (fused): 16 candidates/block, 32 segments ----
    {
        int nactive = (C + 15) >> 4;               // candidate groups of 16
        if (blockIdx.x < nactive) {
            // stage all keys once (C <= 6144 fits the 48 KB cache)
            for (int i = tid; i < C; i += TPB) sk[i] = g_cand[i];
            __syncthreads();

            const int j = tid & 15;                // candidate slot in group
            const int seg = tid >> 4;              // segment 0..31
            const int segsz = (C + 31) >> 5;
            const int lo = seg * segsz;
            int hi = lo + segsz; if (hi > C) hi = C;

            for (int g = blockIdx.x; g * 16 < C; g += nb) {
                int jg = g * 16 + j;
                unsigned long long pk = (jg < C) ? sk[jg] : ~0ull;
                int part = 0;
                int i = lo;
                for (; i + 4 <= hi; i += 4) {
                    part += (sk[i + 0] > pk);
                    part += (sk[i + 1] > pk);
                    part += (sk[i + 2] > pk);
                    part += (sk[i + 3] > pk);
                }
                for (; i < hi; i++) part += (sk[i] > pk);
                ss[tid] = (unsigned int)part;
                __syncthreads();
                if (tid < 16) {
                    int rk = -1, idx = 0;
                    float tv = 0.f;
                    if (jg < C) {
                        int rank = 0;
                        #pragma unroll
                        for (int s = 0; s < 32; s++) rank += (int)ss[s * 16 + tid];
                        if (rank < KTOP) {
                            unsigned int key = (unsigned int)(pk >> 32);
                            unsigned int u = (key & 0x80000000u) ? (key ^ 0x80000000u) : ~key;
                            rk = rank;
                            idx = (int)(~(unsigned int)(pk & 0xFFFFFFFFull));
                            tv = tanhf(__uint_as_float(u));
                        }
                    }
                    s_rk[tid] = rk;
                    s_ridx[tid] = idx;
                    s_rt[tid] = tv;
                }
                __syncthreads();
                // gather + write: 32 lanes per candidate, one float4 each
                {
                    int c = tid >> 5;              // 0..15
                    int rk = s_rk[c];
                    if (rk >= 0) {
                        int idx = s_ridx[c];
                        float tv = s_rt[c];
                        float4 v = x4[(size_t)idx * 32 + lane];
                        reinterpret_cast<float4*>(out)[(size_t)rk * 32 + lane] =
                            make_float4(v.x * tv, v.y * tv, v.z * tv, v.w * tv);
                    }
                }
                __syncthreads();
            }
        }
    }
}

extern "C" void kernel_launch(void* const* d_in, const int* in_sizes, int n_in,
                              void* d_out, int out_size) {
    const float* x = (const float*)d_in[0];
    const float* p = (const float*)d_in[1];
    int n = in_sizes[0] / DD;

    int dev = 0;
    cudaGetDevice(&dev);
    int sm = 0;
    cudaDeviceGetAttribute(&sm, cudaDevAttrMultiProcessorCount, dev);
    int bpsm = 0;
    cudaOccupancyMaxActiveBlocksPerMultiprocessor(&bpsm, mega, TPB, 0);
    if (bpsm < 1) bpsm = 1;
    int nb = sm * bpsm;
    if (nb > NB_CAP) nb = NB_CAP;

    mega<<<nb, TPB>>>(x, p, (float*)d_out, n, nb);
}